// round 7
// baseline (speedup 1.0000x reference)
#include <cuda_runtime.h>
#include <cstdint>

// GraphAttention collapsed form (validated R1-R6, rel_err ~2e-7):
//   v[b,n] = x[b, NEF + n];  c1 = W.a[:64], c2 = W.a[64:]
//   w(i,o) = exp(lrelu(c1*v[i] + c2*v[(i+o)%N])), o in [0,17)
//   denom[b] = sum w;  s[i] = sum_o w*v[(i+o)%N]
//   out[b,i,f] = lrelu(W[f]*s[i]) / denom[b]
//
// R7 = R6 with the denominator exchange converted to a hidden-init mbarrier
// push protocol:
//   * mbarrier.init(8) at start; cluster barrier ARRIVE right after the
//     prologue sync (releases init), WAIT after the reduce (~1200 cyc later,
//     so its ~490-cycle latency is hidden under compute).
//   * warp0 lanes 0-7 push the CTA partial to all peers' slots[rank]
//     (st.shared::cluster) + remote mbarrier.arrive.release.cluster.
//   * all threads try_wait.parity.acquire.cluster on the LOCAL mbar,
//     parity 0 (mbar re-inited every launch -> replay safe).
//   * each warp then sums slots[0..7] itself (xor-shuffle) -- no final
//     __syncthreads, no smem broadcast.

#define NB      8
#define NN      4096
#define NOFF    17
#define FOUT    64
#define NEF     4096
#define CPB     8
#define TPB     512
#define BNODES  512
#define GRID    (NB * CPB)

__device__ __forceinline__ float lrelu(float z) { return fmaxf(z, 0.01f * z); }

__device__ __forceinline__ float warp_sum(float p) {
#pragma unroll
    for (int off = 16; off > 0; off >>= 1)
        p += __shfl_down_sync(0xffffffffu, p, off);
    return p;
}

__device__ __forceinline__ uint32_t smem_u32(const void* p) {
    uint32_t r;
    asm("{ .reg .u64 t; cvta.to.shared.u64 t, %1; cvt.u32.u64 %0, t; }"
        : "=r"(r) : "l"(p));
    return r;
}

__global__ void __launch_bounds__(TPB, 1) __cluster_dims__(CPB, 1, 1)
ga_fused(const float* __restrict__ x,
         const float* __restrict__ W,
         const float* __restrict__ a,
         float* __restrict__ out) {
    __shared__ float sv[BNODES + 16];
    __shared__ float ssn[BNODES];
    __shared__ float sW[FOUT];
    __shared__ float sred[16];
    __shared__ float sc[2];
    __shared__ float slots[CPB];           // inbound partials, one per rank
    __shared__ __align__(8) uint64_t mbar;

    const int b    = blockIdx.x >> 3;
    const int rank = blockIdx.x & (CPB - 1);
    const int base = rank * BNODES;
    const float* v = x + (size_t)b * (NEF + NN) + NEF;
    const int t    = threadIdx.x;
    const int warp = t >> 5;
    const int lane = t & 31;

    const uint32_t mbar_a = smem_u32(&mbar);
    if (t == 0)
        asm volatile("mbarrier.init.shared.b64 [%0], %1;"
                     :: "r"(mbar_a), "r"((uint32_t)CPB) : "memory");

    // Parallel prologue (disjoint warp roles):
    sv[t] = v[(base + t) & (NN - 1)];
    if (t < 16) sv[BNODES + t] = v[(base + BNODES + t) & (NN - 1)];
    if (warp == 14) {            // c1 = W . a[:64]
        float p = fmaf(W[lane], a[lane], W[lane + 32] * a[lane + 32]);
        p = warp_sum(p);
        if (lane == 0) sc[0] = p;
    } else if (warp == 15) {     // c2 = W . a[64:]
        float p = fmaf(W[lane], a[64 + lane], W[lane + 32] * a[96 + lane]);
        p = warp_sum(p);
        if (lane == 0) sc[1] = p;
    } else if (warp == 13) {
        sW[lane]      = W[lane];
        sW[lane + 32] = W[lane + 32];
    }
    __syncthreads();             // sv/sc/sW/mbar-init complete

    // Release mbar init to the cluster; the matching wait comes after the
    // reduce, so the barrier's latency hides under ~1200 cycles of compute.
    asm volatile("barrier.cluster.arrive.aligned;" ::: "memory");

    // Store-phase weights hoisted (constant per thread).
    const float4 wvec = ((const float4*)sW)[t & 15];

    // Phase 1: per-node numerator + thread-local exp-sum (1 node/thread).
    const float c1 = sc[0], c2 = sc[1];
    const float vi = sv[t];
    float esum = 0.0f, s = 0.0f;
#pragma unroll
    for (int o = 0; o < NOFF; o++) {
        const float vj = sv[t + o];
        const float w  = __expf(lrelu(fmaf(c1, vi, c2 * vj)));
        esum += w;
        s = fmaf(w, vj, s);
    }
    ssn[t] = s;

    const float ws = warp_sum(esum);
    if (lane == 0) sred[warp] = ws;
    __syncthreads();             // ssn + sred complete

    // Init-visibility barrier: nearly free by now.
    asm volatile("barrier.cluster.wait.aligned;" ::: "memory");

    // Warp 0: combine 16 warp-partials (butterfly -> all lanes hold total),
    // lanes 0-7 push to every peer's slots[rank] + remote arrive (release).
    if (warp == 0) {
        float p = (lane < 16) ? sred[lane] : 0.0f;
#pragma unroll
        for (int off = 8; off > 0; off >>= 1)
            p += __shfl_xor_sync(0xffffffffu, p, off);
        if (lane < CPB) {
            const uint32_t laddr = smem_u32(&slots[rank]);
            uint32_t rs, rm;
            asm("mapa.shared::cluster.u32 %0, %1, %2;"
                : "=r"(rs) : "r"(laddr), "r"((uint32_t)lane));
            asm volatile("st.shared::cluster.f32 [%0], %1;"
                         :: "r"(rs), "f"(p) : "memory");
            asm("mapa.shared::cluster.u32 %0, %1, %2;"
                : "=r"(rm) : "r"(mbar_a), "r"((uint32_t)lane));
            asm volatile("mbarrier.arrive.release.cluster.shared::cluster.b64 _, [%0];"
                         :: "r"(rm) : "memory");
        }
    }

    // All threads wait for the 8 inbound partials (parity 0: re-inited every
    // launch). Acquire at cluster scope makes the remote stores visible.
    {
        uint32_t done;
        asm volatile(
            "{\n\t.reg .pred p;\n\t"
            "mbarrier.try_wait.parity.acquire.cluster.shared::cta.b64 p, [%1], %2;\n\t"
            "selp.b32 %0, 1, 0, p;\n\t}"
            : "=r"(done) : "r"(mbar_a), "r"(0u) : "memory");
        if (!done) {
            asm volatile(
                "{\n\t.reg .pred P1;\n\t"
                "WAIT_LOOP_%=:\n\t"
                "mbarrier.try_wait.parity.acquire.cluster.shared::cta.b64 P1, [%0], %1, 0x989680;\n\t"
                "@P1 bra.uni WAIT_DONE_%=;\n\t"
                "bra.uni WAIT_LOOP_%=;\n\t"
                "WAIT_DONE_%=:\n\t}"
                :: "r"(mbar_a), "r"(0u) : "memory");
        }
    }

    // Every warp sums the 8 slots itself: p = slots[lane&7], xor 4/2/1.
    // Fixed shuffle order -> deterministic. No block sync, no smem broadcast.
    float p = slots[lane & 7];
#pragma unroll
    for (int off = 4; off > 0; off >>= 1)
        p += __shfl_xor_sync(0xffffffffu, p, off);
    const float inv = 1.0f / p;

    // Phase 2: 512 nodes x 64 feats = 8192 float4, fully coalesced.
    float4* o4 = (float4*)(out + ((size_t)b * NN + base) * FOUT);
    const int nbase = t >> 4;
#pragma unroll
    for (int k = 0; k < 16; k++) {
        const float sn = ssn[nbase + k * 32] * inv;
        float4 r;
        r.x = lrelu(sn * wvec.x);
        r.y = lrelu(sn * wvec.y);
        r.z = lrelu(sn * wvec.z);
        r.w = lrelu(sn * wvec.w);
        o4[t + k * TPB] = r;
    }
}

extern "C" void kernel_launch(void* const* d_in, const int* in_sizes, int n_in,
                              void* d_out, int out_size) {
    const float* x = (const float*)d_in[0];
    const float* W = (const float*)d_in[1];
    const float* a = (const float*)d_in[2];
    float* out = (float*)d_out;

    ga_fused<<<GRID, TPB>>>(x, W, a, out);
}

// round 8
// speedup vs baseline: 1.0332x; 1.0332x over previous
#include <cuda_runtime.h>
#include <cstdint>

// GraphAttention collapsed form (validated R1-R7, rel_err ~2e-7):
//   v[b,n] = x[b, NEF + n];  c1 = W.a[:64], c2 = W.a[64:]
//   w(i,o) = exp(lrelu(c1*v[i] + c2*v[(i+o)%N])), o in [0,17)
//   denom[b] = sum w;  s[i] = sum_o w*v[(i+o)%N]
//   out[b,i,f] = lrelu(W[f]*s[i]) / denom[b]
//
// R8 = R7 skeleton (best in-kernel: 8.0us) + issue-slot trims:
//   * exp2 transform: exp(lrelu(e)) = exp2(lrelu(e*log2e)); c1,c2 premultiplied
//     by log2e in the c-warps -> edge loop uses bare MUFU.EX2 (no FMUL).
//   * inv folded into wvec once (lrelu pos-homogeneous) -> store loop has no
//     per-iteration sn*inv multiply.
// Exchange protocol unchanged: hidden-init mbarrier, cluster push, local sum.

#define NB      8
#define NN      4096
#define NOFF    17
#define FOUT    64
#define NEF     4096
#define CPB     8
#define TPB     512
#define BNODES  512
#define GRID    (NB * CPB)
#define LOG2E   1.4426950408889634f

__device__ __forceinline__ float lrelu(float z) { return fmaxf(z, 0.01f * z); }

__device__ __forceinline__ float warp_sum(float p) {
#pragma unroll
    for (int off = 16; off > 0; off >>= 1)
        p += __shfl_down_sync(0xffffffffu, p, off);
    return p;
}

__device__ __forceinline__ uint32_t smem_u32(const void* p) {
    uint32_t r;
    asm("{ .reg .u64 t; cvta.to.shared.u64 t, %1; cvt.u32.u64 %0, t; }"
        : "=r"(r) : "l"(p));
    return r;
}

__global__ void __launch_bounds__(TPB, 1) __cluster_dims__(CPB, 1, 1)
ga_fused(const float* __restrict__ x,
         const float* __restrict__ W,
         const float* __restrict__ a,
         float* __restrict__ out) {
    __shared__ float sv[BNODES + 16];
    __shared__ float ssn[BNODES];
    __shared__ float sW[FOUT];
    __shared__ float sred[16];
    __shared__ float sc[2];
    __shared__ float slots[CPB];           // inbound partials, one per rank
    __shared__ __align__(8) uint64_t mbar;

    const int b    = blockIdx.x >> 3;
    const int rank = blockIdx.x & (CPB - 1);
    const int base = rank * BNODES;
    const float* v = x + (size_t)b * (NEF + NN) + NEF;
    const int t    = threadIdx.x;
    const int warp = t >> 5;
    const int lane = t & 31;

    const uint32_t mbar_a = smem_u32(&mbar);
    if (t == 0)
        asm volatile("mbarrier.init.shared.b64 [%0], %1;"
                     :: "r"(mbar_a), "r"((uint32_t)CPB) : "memory");

    // Parallel prologue (disjoint warp roles):
    sv[t] = v[(base + t) & (NN - 1)];
    if (t < 16) sv[BNODES + t] = v[(base + BNODES + t) & (NN - 1)];
    if (warp == 14) {            // c1 = (W . a[:64]) * log2e
        float p = fmaf(W[lane], a[lane], W[lane + 32] * a[lane + 32]);
        p = warp_sum(p);
        if (lane == 0) sc[0] = p * LOG2E;
    } else if (warp == 15) {     // c2 = (W . a[64:]) * log2e
        float p = fmaf(W[lane], a[64 + lane], W[lane + 32] * a[96 + lane]);
        p = warp_sum(p);
        if (lane == 0) sc[1] = p * LOG2E;
    } else if (warp == 13) {
        sW[lane]      = W[lane];
        sW[lane + 32] = W[lane + 32];
    }
    __syncthreads();             // sv/sc/sW/mbar-init complete

    // Release mbar init to the cluster; the matching wait comes after the
    // reduce, so the barrier's latency hides under compute.
    asm volatile("barrier.cluster.arrive.aligned;" ::: "memory");

    // Store-phase weights hoisted (constant per thread).
    const float4 wvec = ((const float4*)sW)[t & 15];

    // Phase 1: per-node numerator + thread-local exp-sum (1 node/thread).
    // e is in log2 units; exp2(lrelu(e)) == exp(lrelu(e_natural)).
    const float c1 = sc[0], c2 = sc[1];
    const float vi = sv[t];
    const float c1vi = c1 * vi;
    float esum = 0.0f, s = 0.0f;
#pragma unroll
    for (int o = 0; o < NOFF; o++) {
        const float vj = sv[t + o];
        const float w  = exp2f(lrelu(fmaf(c2, vj, c1vi)));
        esum += w;
        s = fmaf(w, vj, s);
    }
    ssn[t] = s;

    const float ws = warp_sum(esum);
    if (lane == 0) sred[warp] = ws;
    __syncthreads();             // ssn + sred complete

    // Init-visibility barrier: nearly free by now.
    asm volatile("barrier.cluster.wait.aligned;" ::: "memory");

    // Warp 0: combine 16 warp-partials (butterfly -> all lanes hold total),
    // lanes 0-7 push to every peer's slots[rank] + remote arrive (release).
    if (warp == 0) {
        float p = (lane < 16) ? sred[lane] : 0.0f;
#pragma unroll
        for (int off = 8; off > 0; off >>= 1)
            p += __shfl_xor_sync(0xffffffffu, p, off);
        if (lane < CPB) {
            const uint32_t laddr = smem_u32(&slots[rank]);
            uint32_t rs, rm;
            asm("mapa.shared::cluster.u32 %0, %1, %2;"
                : "=r"(rs) : "r"(laddr), "r"((uint32_t)lane));
            asm volatile("st.shared::cluster.f32 [%0], %1;"
                         :: "r"(rs), "f"(p) : "memory");
            asm("mapa.shared::cluster.u32 %0, %1, %2;"
                : "=r"(rm) : "r"(mbar_a), "r"((uint32_t)lane));
            asm volatile("mbarrier.arrive.release.cluster.shared::cluster.b64 _, [%0];"
                         :: "r"(rm) : "memory");
        }
    }

    // All threads wait for the 8 inbound partials (parity 0: re-inited every
    // launch -> graph-replay safe). Acquire makes the remote stores visible.
    {
        uint32_t done;
        asm volatile(
            "{\n\t.reg .pred p;\n\t"
            "mbarrier.try_wait.parity.acquire.cluster.shared::cta.b64 p, [%1], %2;\n\t"
            "selp.b32 %0, 1, 0, p;\n\t}"
            : "=r"(done) : "r"(mbar_a), "r"(0u) : "memory");
        if (!done) {
            asm volatile(
                "{\n\t.reg .pred P1;\n\t"
                "WAIT_LOOP_%=:\n\t"
                "mbarrier.try_wait.parity.acquire.cluster.shared::cta.b64 P1, [%0], %1, 0x989680;\n\t"
                "@P1 bra.uni WAIT_DONE_%=;\n\t"
                "bra.uni WAIT_LOOP_%=;\n\t"
                "WAIT_DONE_%=:\n\t}"
                :: "r"(mbar_a), "r"(0u) : "memory");
        }
    }

    // Every warp sums the 8 slots itself (fixed shuffle order, deterministic),
    // then folds 1/denom into the weight vector ONCE.
    float p = slots[lane & 7];
#pragma unroll
    for (int off = 4; off > 0; off >>= 1)
        p += __shfl_xor_sync(0xffffffffu, p, off);
    const float inv = 1.0f / p;
    const float4 wv = make_float4(wvec.x * inv, wvec.y * inv,
                                  wvec.z * inv, wvec.w * inv);

    // Phase 2: 512 nodes x 64 feats = 8192 float4, fully coalesced.
    float4* o4 = (float4*)(out + ((size_t)b * NN + base) * FOUT);
    const int nbase = t >> 4;
#pragma unroll
    for (int k = 0; k < 16; k++) {
        const float sn = ssn[nbase + k * 32];
        float4 r;
        r.x = lrelu(sn * wv.x);
        r.y = lrelu(sn * wv.y);
        r.z = lrelu(sn * wv.z);
        r.w = lrelu(sn * wv.w);
        o4[t + k * TPB] = r;
    }
}

extern "C" void kernel_launch(void* const* d_in, const int* in_sizes, int n_in,
                              void* d_out, int out_size) {
    const float* x = (const float*)d_in[0];
    const float* W = (const float*)d_in[1];
    const float* a = (const float*)d_in[2];
    float* out = (float*)d_out;

    ga_fused<<<GRID, TPB>>>(x, W, a, out);
}